// round 12
// baseline (speedup 1.0000x reference)
#include <cuda_runtime.h>

#define N_NODES 100000
#define N_EDGES 800000
#define N_LABEL 400000
#define CH      256
#define H1      128
#define H2      32

#define SCAN_CHUNK 512
#define NBLK_SCAN  ((N_NODES + SCAN_CHUNK - 1) / SCAN_CHUNK)   // 196

// Scratch (module-load allocated; allowed per harness rules)
__device__ __align__(16) float g_xw[(size_t)N_NODES * CH];
__device__ __align__(16) float g_y[(size_t)N_NODES * H1];
__device__ __align__(16) float g_z[(size_t)N_NODES * H1];
__device__ float g_dis[N_NODES];
__device__ int   g_cnt[N_NODES];
__device__ int   g_rowptr[N_NODES + 1];
__device__ int   g_cursor[N_NODES];
__device__ int   g_csrc[N_EDGES];
__device__ int   g_partial[NBLK_SCAN];
__device__ int   g_poff[NBLK_SCAN];

// ---------------------------------------------------------------------------
// tf32 mma helpers (m16n8k8, row.col, fp32 accumulate)
// ---------------------------------------------------------------------------
__device__ __forceinline__ unsigned f2tf(float f) {
    unsigned r;
    asm("cvt.rna.tf32.f32 %0, %1;" : "=r"(r) : "f"(f));
    return r;
}

__device__ __forceinline__ uint4 f2tf4(float4 v) {
    return make_uint4(f2tf(v.x), f2tf(v.y), f2tf(v.z), f2tf(v.w));
}

__device__ __forceinline__ void mma_tf32(float* c, const unsigned* a,
                                         unsigned b0, unsigned b1) {
    asm("mma.sync.aligned.m16n8k8.row.col.f32.tf32.tf32.f32 "
        "{%0,%1,%2,%3},{%4,%5,%6,%7},{%8,%9},{%0,%1,%2,%3};"
        : "+f"(c[0]), "+f"(c[1]), "+f"(c[2]), "+f"(c[3])
        : "r"(a[0]), "r"(a[1]), "r"(a[2]), "r"(a[3]), "r"(b0), "r"(b1));
}

// ---------------------------------------------------------------------------
// Pipelined tf32 GEMM, smem-BW-optimized: OUT[Nx ND] = X[Nx256] @ W[256 x ND].
// Block tile 128M x 128N, 8 warps (4m x 2n), warp tile 32x64 (192 B/HMMA).
// k-chunks of 32, double-buffered smem, reg prefetch, 1 sync per chunk.
// sA stride 36 fl (banks 4*lr+lc), sB stride 136 fl (banks 8*lc+lr): clean.
// ---------------------------------------------------------------------------
#define GA_F     (128 * 36)
#define GB_F     (32 * 136)
#define GBUF2_F  (GA_F + GB_F)                 // 8960 words per buffer
#define GSMEM2_B (2 * GBUF2_F * 4)             // 71680 bytes

template<int ND>
__global__ void __launch_bounds__(256)
gemm_tf32(const float* __restrict__ X, const float* __restrict__ W,
          float* __restrict__ OUT) {
    extern __shared__ __align__(16) unsigned smu[];
    const int tid = threadIdx.x;
    const int lane = tid & 31, warp = tid >> 5;
    const int warp_m = warp >> 1, warp_n = warp & 1;
    const int row0 = blockIdx.y * 128, col0 = blockIdx.x * 128;
    const int lr = lane >> 2, lc = lane & 3;

    // staging coordinates: A 1024 f4 (r=idx>>3, c4=idx&7), B 1024 f4 (k=idx>>5, c4=idx&31)
    const int ar = tid >> 3, ac4 = tid & 7;
    const int bk = tid >> 5, bc4 = tid & 31;

    float c[2][8][4];
    #pragma unroll
    for (int mt = 0; mt < 2; mt++)
        #pragma unroll
        for (int nt = 0; nt < 8; nt++)
            #pragma unroll
            for (int i = 0; i < 4; i++) c[mt][nt][i] = 0.f;

    float4 ra[4], rb[4];

    // prologue: chunk 0
    #pragma unroll
    for (int it = 0; it < 4; it++) {
        int grow = row0 + ar + 32 * it;
        ra[it] = make_float4(0.f, 0.f, 0.f, 0.f);
        if (grow < N_NODES)
            ra[it] = *(const float4*)&X[(size_t)grow * CH + ac4 * 4];
    }
    #pragma unroll
    for (int it = 0; it < 4; it++)
        rb[it] = *(const float4*)&W[(size_t)(bk + 8 * it) * ND + col0 + bc4 * 4];

    int buf = 0;
    for (int cch = 0; cch < 8; cch++) {
        unsigned* sA = smu + buf * GBUF2_F;
        unsigned* sB = sA + GA_F;
        #pragma unroll
        for (int it = 0; it < 4; it++)
            ((uint4*)sA)[(ar + 32 * it) * 9 + ac4] = f2tf4(ra[it]);
        #pragma unroll
        for (int it = 0; it < 4; it++)
            ((uint4*)sB)[(bk + 8 * it) * 34 + bc4] = f2tf4(rb[it]);
        __syncthreads();

        if (cch < 7) {
            int k0 = (cch + 1) * 32;
            #pragma unroll
            for (int it = 0; it < 4; it++) {
                int grow = row0 + ar + 32 * it;
                ra[it] = make_float4(0.f, 0.f, 0.f, 0.f);
                if (grow < N_NODES)
                    ra[it] = *(const float4*)&X[(size_t)grow * CH + k0 + ac4 * 4];
            }
            #pragma unroll
            for (int it = 0; it < 4; it++)
                rb[it] = *(const float4*)&W[(size_t)(k0 + bk + 8 * it) * ND + col0 + bc4 * 4];
        }

        #pragma unroll
        for (int k8 = 0; k8 < 4; k8++) {
            int kc = k8 * 8 + lc;
            unsigned a[2][4];
            #pragma unroll
            for (int mt = 0; mt < 2; mt++) {
                int r = warp_m * 32 + mt * 16 + lr;
                a[mt][0] = sA[r * 36 + kc];
                a[mt][1] = sA[(r + 8) * 36 + kc];
                a[mt][2] = sA[r * 36 + kc + 4];
                a[mt][3] = sA[(r + 8) * 36 + kc + 4];
            }
            #pragma unroll
            for (int nt = 0; nt < 8; nt++) {
                int cb = warp_n * 64 + nt * 8 + lr;
                unsigned b0 = sB[kc * 136 + cb];
                unsigned b1 = sB[(kc + 4) * 136 + cb];
                mma_tf32(c[0][nt], a[0], b0, b1);
                mma_tf32(c[1][nt], a[1], b0, b1);
            }
        }
        buf ^= 1;
    }

    #pragma unroll
    for (int mt = 0; mt < 2; mt++) {
        int r0 = row0 + warp_m * 32 + mt * 16 + lr;
        #pragma unroll
        for (int nt = 0; nt < 8; nt++) {
            int cc = col0 + warp_n * 64 + nt * 8 + 2 * lc;
            if (r0 < N_NODES)
                *(float2*)&OUT[(size_t)r0 * ND + cc] = make_float2(c[mt][nt][0], c[mt][nt][1]);
            if (r0 + 8 < N_NODES)
                *(float2*)&OUT[(size_t)(r0 + 8) * ND + cc] = make_float2(c[mt][nt][2], c[mt][nt][3]);
        }
    }
}

// ---------------------------------------------------------------------------
// CSR build: histogram -> 3-pass exclusive scan -> bucket fill
// ---------------------------------------------------------------------------
__global__ void zero_cnt() {
    int i = blockIdx.x * blockDim.x + threadIdx.x;
    if (i < N_NODES) g_cnt[i] = 0;
}

__global__ void hist(const int* __restrict__ ei) {
    int e = blockIdx.x * blockDim.x + threadIdx.x;
    if (e >= N_EDGES) return;
    int d = ei[N_EDGES + e];
    if ((unsigned)d < N_NODES) atomicAdd(&g_cnt[d], 1);
}

__global__ void __launch_bounds__(SCAN_CHUNK) scan1() {
    __shared__ int s[SCAN_CHUNK];
    int tid = threadIdx.x;
    int i = blockIdx.x * SCAN_CHUNK + tid;
    s[tid] = (i < N_NODES) ? g_cnt[i] : 0;
    __syncthreads();
    #pragma unroll
    for (int off = SCAN_CHUNK / 2; off > 0; off >>= 1) {
        if (tid < off) s[tid] += s[tid + off];
        __syncthreads();
    }
    if (tid == 0) g_partial[blockIdx.x] = s[0];
}

__global__ void __launch_bounds__(256) scan2() {
    __shared__ int s[256];
    int tid = threadIdx.x;
    int v = (tid < NBLK_SCAN) ? g_partial[tid] : 0;
    s[tid] = v;
    __syncthreads();
    #pragma unroll
    for (int off = 1; off < 256; off <<= 1) {
        int t = (tid >= off) ? s[tid - off] : 0;
        __syncthreads();
        s[tid] += t;
        __syncthreads();
    }
    if (tid < NBLK_SCAN) g_poff[tid] = s[tid] - v;
    if (tid == NBLK_SCAN - 1) g_rowptr[N_NODES] = s[tid];
}

__global__ void __launch_bounds__(SCAN_CHUNK) scan3() {
    __shared__ int s[SCAN_CHUNK];
    int tid = threadIdx.x;
    int i = blockIdx.x * SCAN_CHUNK + tid;
    int c = (i < N_NODES) ? g_cnt[i] : 0;
    s[tid] = c;
    __syncthreads();
    #pragma unroll
    for (int off = 1; off < SCAN_CHUNK; off <<= 1) {
        int t = (tid >= off) ? s[tid - off] : 0;
        __syncthreads();
        s[tid] += t;
        __syncthreads();
    }
    if (i < N_NODES) {
        int excl = g_poff[blockIdx.x] + s[tid] - c;
        g_rowptr[i] = excl;
        g_cursor[i] = excl;
        g_dis[i] = rsqrtf((float)(c + 1));
    }
}

__global__ void fill(const int* __restrict__ ei) {
    int e = blockIdx.x * blockDim.x + threadIdx.x;
    if (e >= N_EDGES) return;
    int src = ei[e];
    int dst = ei[N_EDGES + e];
    if ((unsigned)src >= N_NODES || (unsigned)dst >= N_NODES) return;
    int p = atomicAdd(&g_cursor[dst], 1);
    g_csrc[p] = src;
}

// ---------------------------------------------------------------------------
// Gather on y (128-wide): z[i] = dis_i*(dis_i*y[i] + sum_{s in in(i)} dis_s*y[s])
// (b_gcn@W1 term cancels in the edge difference, so it is omitted.)
// Warp per node; lane owns exactly one float4 of the 128-wide row.
// ---------------------------------------------------------------------------
__global__ void __launch_bounds__(256) gather128() {
    int node = blockIdx.x * 8 + (threadIdx.x >> 5);
    if (node >= N_NODES) return;
    int lane = threadIdx.x & 31;
    const float4* y4 = (const float4*)g_y;

    float di = g_dis[node];
    float4 v = y4[(size_t)node * 32 + lane];
    float4 acc = make_float4(di * v.x, di * v.y, di * v.z, di * v.w);

    int beg = g_rowptr[node], end = g_rowptr[node + 1];
    for (int j = beg; j < end; j++) {
        int s = g_csrc[j];
        float cc = g_dis[s];
        float4 w = y4[(size_t)s * 32 + lane];
        acc.x += cc * w.x; acc.y += cc * w.y;
        acc.z += cc * w.z; acc.w += cc * w.w;
    }

    ((float4*)g_z)[(size_t)node * 32 + lane] =
        make_float4(di * acc.x, di * acc.y, di * acc.z, di * acc.w);
}

// ---------------------------------------------------------------------------
// Edge MLP (unchanged from round-9/10 PASS): 128 edges/block, layer-2 on mma.
// ---------------------------------------------------------------------------
#define TE2       128
#define SO2_STR   132
#define SW2_STR   40
#define MLP2_SMEM_W (TE2 * SO2_STR + H1 * SW2_STR)
#define MLP2_SMEM_B (MLP2_SMEM_W * 4)

__global__ void __launch_bounds__(256)
mlp2_kernel(const int* __restrict__ eli,
            const float* __restrict__ b1, const float* __restrict__ W2,
            const float* __restrict__ b2, const float* __restrict__ W3,
            const float* __restrict__ b3, float* __restrict__ out) {
    extern __shared__ __align__(16) unsigned smu[];
    __shared__ int sIdx[2 * TE2];

    unsigned* sO  = smu;
    unsigned* sW2 = smu + TE2 * SO2_STR;

    const int tid  = threadIdx.x;
    const int lane = tid & 31, warp = tid >> 5;
    const int lr = lane >> 2, lc = lane & 3;
    const int tile0 = blockIdx.x * TE2;

    if (tid < TE2) {
        int v = eli[tile0 + tid];
        sIdx[tid] = ((unsigned)v < N_NODES) ? v : 0;
    } else {
        int v = eli[N_LABEL + tile0 + tid - TE2];
        sIdx[tid] = ((unsigned)v < N_NODES) ? v : 0;
    }
    __syncthreads();

    const float4* z4  = (const float4*)g_z;
    const float4* b14 = (const float4*)b1;
    #pragma unroll
    for (int it = 0; it < 16; it++) {
        int idx = tid + 256 * it;
        int e = idx >> 5, c4 = idx & 31;
        int a = sIdx[e], b = sIdx[TE2 + e];
        float4 va = z4[(size_t)a * 32 + c4];
        float4 vb = z4[(size_t)b * 32 + c4];
        float4 bi = b14[c4];
        ((uint4*)sO)[e * 33 + c4] = make_uint4(
            f2tf(fmaxf(vb.x - va.x + bi.x, 0.f)),
            f2tf(fmaxf(vb.y - va.y + bi.y, 0.f)),
            f2tf(fmaxf(vb.z - va.z + bi.z, 0.f)),
            f2tf(fmaxf(vb.w - va.w + bi.w, 0.f)));
    }
    #pragma unroll
    for (int it = 0; it < 16; it++) {
        int idx = tid + 256 * it;
        int k = idx >> 5, n = idx & 31;
        sW2[k * SW2_STR + n] = f2tf(W2[idx]);
    }
    __syncthreads();

    float c[4][4];
    #pragma unroll
    for (int nt = 0; nt < 4; nt++)
        #pragma unroll
        for (int i = 0; i < 4; i++) c[nt][i] = 0.f;

    #pragma unroll
    for (int k8 = 0; k8 < 16; k8++) {
        int kc = k8 * 8 + lc;
        int r = warp * 16 + lr;
        unsigned a[4];
        a[0] = sO[r * SO2_STR + kc];
        a[1] = sO[(r + 8) * SO2_STR + kc];
        a[2] = sO[r * SO2_STR + kc + 4];
        a[3] = sO[(r + 8) * SO2_STR + kc + 4];
        #pragma unroll
        for (int nt = 0; nt < 4; nt++) {
            int cb = nt * 8 + lr;
            unsigned b0 = sW2[kc * SW2_STR + cb];
            unsigned b1v = sW2[(kc + 4) * SW2_STR + cb];
            mma_tf32(c[nt], a, b0, b1v);
        }
    }

    const float b3r = b3[0];
    float p0 = 0.f, p1 = 0.f;
    #pragma unroll
    for (int nt = 0; nt < 4; nt++) {
        int n0 = nt * 8 + 2 * lc;
        float b20 = b2[n0], b21 = b2[n0 + 1];
        float w30 = W3[n0], w31 = W3[n0 + 1];
        p0 += fmaxf(c[nt][0] + b20, 0.f) * w30 + fmaxf(c[nt][1] + b21, 0.f) * w31;
        p1 += fmaxf(c[nt][2] + b20, 0.f) * w30 + fmaxf(c[nt][3] + b21, 0.f) * w31;
    }
    p0 += __shfl_xor_sync(0xffffffffu, p0, 1);
    p0 += __shfl_xor_sync(0xffffffffu, p0, 2);
    p1 += __shfl_xor_sync(0xffffffffu, p1, 1);
    p1 += __shfl_xor_sync(0xffffffffu, p1, 2);
    if (lc == 0) {
        int r = tile0 + warp * 16 + lr;
        out[r] = p0 + b3r;
        out[r + 8] = p1 + b3r;
    }
}

// ---------------------------------------------------------------------------
// Host: resolve inputs BY ELEMENT COUNT; gemm_tf32<256> is launch #4.
// ---------------------------------------------------------------------------
extern "C" void kernel_launch(void* const* d_in, const int* in_sizes, int n_in,
                              void* d_out, int out_size) {
    const float *x = 0, *W_gcn = 0, *b_gcn = 0, *W1 = 0, *b1 = 0, *W2 = 0,
                *b2 = 0, *W3 = 0, *b3 = 0;
    const int *ei = 0, *eli = 0;
    int idx32[2] = {-1, -1};
    int n32 = 0, i128 = -1;

    for (int i = 0; i < n_in; i++) {
        switch (in_sizes[i]) {
            case 25600000: x     = (const float*)d_in[i]; break;
            case 1600000:  ei    = (const int*)d_in[i];   break;
            case 800000:   eli   = (const int*)d_in[i];   break;
            case 65536:    W_gcn = (const float*)d_in[i]; break;
            case 32768:    W1    = (const float*)d_in[i]; break;
            case 4096:     W2    = (const float*)d_in[i]; break;
            case 256:      b_gcn = (const float*)d_in[i]; break;
            case 128:      b1    = (const float*)d_in[i]; i128 = i; break;
            case 32:       if (n32 < 2) idx32[n32] = i; n32++; break;
            case 1:        b3    = (const float*)d_in[i]; break;
            default: break;
        }
    }
    if (n32 >= 2) {
        if (idx32[0] < i128) {
            W3 = (const float*)d_in[idx32[0]];
            b2 = (const float*)d_in[idx32[1]];
        } else {
            b2 = (const float*)d_in[idx32[0]];
            W3 = (const float*)d_in[idx32[1]];
        }
    }
    if (!x)     x     = (const float*)d_in[0];
    if (!ei)    ei    = (const int*)d_in[1];
    if (!eli)   eli   = (const int*)d_in[2];
    if (!W_gcn) W_gcn = (const float*)d_in[3];
    if (!b_gcn) b_gcn = (const float*)d_in[4];
    if (!W1)    W1    = (const float*)d_in[5];
    if (!b1)    b1    = (const float*)d_in[6];
    if (!W2)    W2    = (const float*)d_in[7];
    if (!b2)    b2    = (const float*)d_in[8];
    if (!W3)    W3    = (const float*)d_in[9];
    if (!b3)    b3    = (const float*)d_in[10];
    float* out = (float*)d_out;

    cudaFuncSetAttribute(gemm_tf32<CH>, cudaFuncAttributeMaxDynamicSharedMemorySize,
                         GSMEM2_B);
    cudaFuncSetAttribute(gemm_tf32<H1>, cudaFuncAttributeMaxDynamicSharedMemorySize,
                         GSMEM2_B);
    cudaFuncSetAttribute(mlp2_kernel, cudaFuncAttributeMaxDynamicSharedMemorySize,
                         MLP2_SMEM_B);

    float* xw = 0;
    cudaGetSymbolAddress((void**)&xw, g_xw);
    float* y = 0;
    cudaGetSymbolAddress((void**)&y, g_y);

    zero_cnt<<<(N_NODES + 255) / 256, 256>>>();
    hist<<<(N_EDGES + 255) / 256, 256>>>(ei);
    scan1<<<NBLK_SCAN, SCAN_CHUNK>>>();

    // launch #4 (ncu window): xw = x @ W_gcn   (block tile 128x128)
    dim3 g1(CH / 128, (N_NODES + 127) / 128);
    gemm_tf32<CH><<<g1, 256, GSMEM2_B>>>(x, W_gcn, xw);

    scan2<<<1, 256>>>();
    scan3<<<NBLK_SCAN, SCAN_CHUNK>>>();
    fill<<<(N_EDGES + 255) / 256, 256>>>(ei);

    // y = xw @ W1  (dense, BEFORE the sparse aggregation; linearity)
    dim3 g2(H1 / 128, (N_NODES + 127) / 128);
    gemm_tf32<H1><<<g2, 256, GSMEM2_B>>>(xw, W1, y);

    gather128<<<(N_NODES + 7) / 8, 256>>>();

    mlp2_kernel<<<N_LABEL / TE2, 256, MLP2_SMEM_B>>>(eli, b1, W2, b2, W3, b3, out);
}

// round 14
// speedup vs baseline: 1.3777x; 1.3777x over previous
#include <cuda_runtime.h>

#define N_NODES 100000
#define N_EDGES 800000
#define N_LABEL 400000
#define CH      256
#define H1      128
#define H2      32

#define SCAN_CHUNK 512
#define NBLK_SCAN  ((N_NODES + SCAN_CHUNK - 1) / SCAN_CHUNK)   // 196

// Scratch (module-load allocated; allowed per harness rules)
__device__ __align__(16) float g_wc[CH * H1];
__device__ __align__(16) float g_y[(size_t)N_NODES * H1];
__device__ __align__(16) float g_z[(size_t)N_NODES * H1];
__device__ float g_dis[N_NODES];
__device__ int   g_cnt[N_NODES];
__device__ int   g_rowptr[N_NODES + 1];
__device__ int   g_cursor[N_NODES];
__device__ int   g_csrc[N_EDGES];
__device__ int   g_partial[NBLK_SCAN];
__device__ int   g_poff[NBLK_SCAN];

// ---------------------------------------------------------------------------
// tf32 mma helpers (m16n8k8, row.col, fp32 accumulate)
// ---------------------------------------------------------------------------
__device__ __forceinline__ unsigned f2tf(float f) {
    unsigned r;
    asm("cvt.rna.tf32.f32 %0, %1;" : "=r"(r) : "f"(f));
    return r;
}

__device__ __forceinline__ uint4 f2tf4(float4 v) {
    return make_uint4(f2tf(v.x), f2tf(v.y), f2tf(v.z), f2tf(v.w));
}

__device__ __forceinline__ void mma_tf32(float* c, const unsigned* a,
                                         unsigned b0, unsigned b1) {
    asm("mma.sync.aligned.m16n8k8.row.col.f32.tf32.tf32.f32 "
        "{%0,%1,%2,%3},{%4,%5,%6,%7},{%8,%9},{%0,%1,%2,%3};"
        : "+f"(c[0]), "+f"(c[1]), "+f"(c[2]), "+f"(c[3])
        : "r"(a[0]), "r"(a[1]), "r"(a[2]), "r"(a[3]), "r"(b0), "r"(b1));
}

// ---------------------------------------------------------------------------
// Wc = W_gcn @ W1   (256x256 @ 256x128, fp32 SIMT — exact, tiny)
// Block = one output row i; thread = output col j.
// ---------------------------------------------------------------------------
__global__ void __launch_bounds__(128)
wc_kernel(const float* __restrict__ Wg, const float* __restrict__ W1) {
    __shared__ float srow[CH];
    int i = blockIdx.x;
    int j = threadIdx.x;
    for (int k = j; k < CH; k += 128) srow[k] = Wg[i * CH + k];
    __syncthreads();
    float acc = 0.f;
    #pragma unroll 8
    for (int k = 0; k < CH; k++) acc += srow[k] * W1[k * H1 + j];
    g_wc[i * H1 + j] = acc;
}

// ---------------------------------------------------------------------------
// Pipelined tf32 GEMM (round-12 PASS): OUT = X[Nx256] @ W[256xND].
// Block tile 128M x 128N, 8 warps (4m x 2n), warp tile 32x64, k-chunks of 32,
// double-buffered smem (tf32 bits, cvt at staging), reg prefetch, 1 sync/chunk.
// ---------------------------------------------------------------------------
#define GA_F     (128 * 36)
#define GB_F     (32 * 136)
#define GBUF2_F  (GA_F + GB_F)                 // 8960 words per buffer
#define GSMEM2_B (2 * GBUF2_F * 4)             // 71680 bytes

template<int ND>
__global__ void __launch_bounds__(256)
gemm_tf32(const float* __restrict__ X, const float* __restrict__ W,
          float* __restrict__ OUT) {
    extern __shared__ __align__(16) unsigned smu[];
    const int tid = threadIdx.x;
    const int lane = tid & 31, warp = tid >> 5;
    const int warp_m = warp >> 1, warp_n = warp & 1;
    const int row0 = blockIdx.y * 128, col0 = blockIdx.x * 128;
    const int lr = lane >> 2, lc = lane & 3;

    const int ar = tid >> 3, ac4 = tid & 7;
    const int bk = tid >> 5, bc4 = tid & 31;

    float c[2][8][4];
    #pragma unroll
    for (int mt = 0; mt < 2; mt++)
        #pragma unroll
        for (int nt = 0; nt < 8; nt++)
            #pragma unroll
            for (int i = 0; i < 4; i++) c[mt][nt][i] = 0.f;

    float4 ra[4], rb[4];

    #pragma unroll
    for (int it = 0; it < 4; it++) {
        int grow = row0 + ar + 32 * it;
        ra[it] = make_float4(0.f, 0.f, 0.f, 0.f);
        if (grow < N_NODES)
            ra[it] = *(const float4*)&X[(size_t)grow * CH + ac4 * 4];
    }
    #pragma unroll
    for (int it = 0; it < 4; it++)
        rb[it] = *(const float4*)&W[(size_t)(bk + 8 * it) * ND + col0 + bc4 * 4];

    int buf = 0;
    for (int cch = 0; cch < 8; cch++) {
        unsigned* sA = smu + buf * GBUF2_F;
        unsigned* sB = sA + GA_F;
        #pragma unroll
        for (int it = 0; it < 4; it++)
            ((uint4*)sA)[(ar + 32 * it) * 9 + ac4] = f2tf4(ra[it]);
        #pragma unroll
        for (int it = 0; it < 4; it++)
            ((uint4*)sB)[(bk + 8 * it) * 34 + bc4] = f2tf4(rb[it]);
        __syncthreads();

        if (cch < 7) {
            int k0 = (cch + 1) * 32;
            #pragma unroll
            for (int it = 0; it < 4; it++) {
                int grow = row0 + ar + 32 * it;
                ra[it] = make_float4(0.f, 0.f, 0.f, 0.f);
                if (grow < N_NODES)
                    ra[it] = *(const float4*)&X[(size_t)grow * CH + k0 + ac4 * 4];
            }
            #pragma unroll
            for (int it = 0; it < 4; it++)
                rb[it] = *(const float4*)&W[(size_t)(k0 + bk + 8 * it) * ND + col0 + bc4 * 4];
        }

        #pragma unroll
        for (int k8 = 0; k8 < 4; k8++) {
            int kc = k8 * 8 + lc;
            unsigned a[2][4];
            #pragma unroll
            for (int mt = 0; mt < 2; mt++) {
                int r = warp_m * 32 + mt * 16 + lr;
                a[mt][0] = sA[r * 36 + kc];
                a[mt][1] = sA[(r + 8) * 36 + kc];
                a[mt][2] = sA[r * 36 + kc + 4];
                a[mt][3] = sA[(r + 8) * 36 + kc + 4];
            }
            #pragma unroll
            for (int nt = 0; nt < 8; nt++) {
                int cb = warp_n * 64 + nt * 8 + lr;
                unsigned b0 = sB[kc * 136 + cb];
                unsigned b1 = sB[(kc + 4) * 136 + cb];
                mma_tf32(c[0][nt], a[0], b0, b1);
                mma_tf32(c[1][nt], a[1], b0, b1);
            }
        }
        buf ^= 1;
    }

    #pragma unroll
    for (int mt = 0; mt < 2; mt++) {
        int r0 = row0 + warp_m * 32 + mt * 16 + lr;
        #pragma unroll
        for (int nt = 0; nt < 8; nt++) {
            int cc = col0 + warp_n * 64 + nt * 8 + 2 * lc;
            if (r0 < N_NODES)
                *(float2*)&OUT[(size_t)r0 * ND + cc] = make_float2(c[mt][nt][0], c[mt][nt][1]);
            if (r0 + 8 < N_NODES)
                *(float2*)&OUT[(size_t)(r0 + 8) * ND + cc] = make_float2(c[mt][nt][2], c[mt][nt][3]);
        }
    }
}

// ---------------------------------------------------------------------------
// CSR build: histogram -> 3-pass exclusive scan -> bucket fill
// ---------------------------------------------------------------------------
__global__ void zero_cnt() {
    int i = blockIdx.x * blockDim.x + threadIdx.x;
    if (i < N_NODES) g_cnt[i] = 0;
}

__global__ void hist(const int* __restrict__ ei) {
    int e = blockIdx.x * blockDim.x + threadIdx.x;
    if (e >= N_EDGES) return;
    int d = ei[N_EDGES + e];
    if ((unsigned)d < N_NODES) atomicAdd(&g_cnt[d], 1);
}

__global__ void __launch_bounds__(SCAN_CHUNK) scan1() {
    __shared__ int s[SCAN_CHUNK];
    int tid = threadIdx.x;
    int i = blockIdx.x * SCAN_CHUNK + tid;
    s[tid] = (i < N_NODES) ? g_cnt[i] : 0;
    __syncthreads();
    #pragma unroll
    for (int off = SCAN_CHUNK / 2; off > 0; off >>= 1) {
        if (tid < off) s[tid] += s[tid + off];
        __syncthreads();
    }
    if (tid == 0) g_partial[blockIdx.x] = s[0];
}

__global__ void __launch_bounds__(256) scan2() {
    __shared__ int s[256];
    int tid = threadIdx.x;
    int v = (tid < NBLK_SCAN) ? g_partial[tid] : 0;
    s[tid] = v;
    __syncthreads();
    #pragma unroll
    for (int off = 1; off < 256; off <<= 1) {
        int t = (tid >= off) ? s[tid - off] : 0;
        __syncthreads();
        s[tid] += t;
        __syncthreads();
    }
    if (tid < NBLK_SCAN) g_poff[tid] = s[tid] - v;
    if (tid == NBLK_SCAN - 1) g_rowptr[N_NODES] = s[tid];
}

__global__ void __launch_bounds__(SCAN_CHUNK) scan3() {
    __shared__ int s[SCAN_CHUNK];
    int tid = threadIdx.x;
    int i = blockIdx.x * SCAN_CHUNK + tid;
    int c = (i < N_NODES) ? g_cnt[i] : 0;
    s[tid] = c;
    __syncthreads();
    #pragma unroll
    for (int off = 1; off < SCAN_CHUNK; off <<= 1) {
        int t = (tid >= off) ? s[tid - off] : 0;
        __syncthreads();
        s[tid] += t;
        __syncthreads();
    }
    if (i < N_NODES) {
        int excl = g_poff[blockIdx.x] + s[tid] - c;
        g_rowptr[i] = excl;
        g_cursor[i] = excl;
        g_dis[i] = rsqrtf((float)(c + 1));
    }
}

__global__ void fill(const int* __restrict__ ei) {
    int e = blockIdx.x * blockDim.x + threadIdx.x;
    if (e >= N_EDGES) return;
    int src = ei[e];
    int dst = ei[N_EDGES + e];
    if ((unsigned)src >= N_NODES || (unsigned)dst >= N_NODES) return;
    int p = atomicAdd(&g_cursor[dst], 1);
    g_csrc[p] = src;
}

// ---------------------------------------------------------------------------
// Gather on y (128-wide): z[i] = dis_i*(dis_i*y[i] + sum_{s in in(i)} dis_s*y[s])
// ---------------------------------------------------------------------------
__global__ void __launch_bounds__(256) gather128() {
    int node = blockIdx.x * 8 + (threadIdx.x >> 5);
    if (node >= N_NODES) return;
    int lane = threadIdx.x & 31;
    const float4* y4 = (const float4*)g_y;

    float di = g_dis[node];
    float4 v = y4[(size_t)node * 32 + lane];
    float4 acc = make_float4(di * v.x, di * v.y, di * v.z, di * v.w);

    int beg = g_rowptr[node], end = g_rowptr[node + 1];
    for (int j = beg; j < end; j++) {
        int s = g_csrc[j];
        float cc = g_dis[s];
        float4 w = y4[(size_t)s * 32 + lane];
        acc.x += cc * w.x; acc.y += cc * w.y;
        acc.z += cc * w.z; acc.w += cc * w.w;
    }

    ((float4*)g_z)[(size_t)node * 32 + lane] =
        make_float4(di * acc.x, di * acc.y, di * acc.z, di * acc.w);
}

// ---------------------------------------------------------------------------
// Edge MLP (round-12 PASS): 128 edges/block, layer-2 on mma.
// ---------------------------------------------------------------------------
#define TE2       128
#define SO2_STR   132
#define SW2_STR   40
#define MLP2_SMEM_W (TE2 * SO2_STR + H1 * SW2_STR)
#define MLP2_SMEM_B (MLP2_SMEM_W * 4)

__global__ void __launch_bounds__(256)
mlp2_kernel(const int* __restrict__ eli,
            const float* __restrict__ b1, const float* __restrict__ W2,
            const float* __restrict__ b2, const float* __restrict__ W3,
            const float* __restrict__ b3, float* __restrict__ out) {
    extern __shared__ __align__(16) unsigned smu[];
    __shared__ int sIdx[2 * TE2];

    unsigned* sO  = smu;
    unsigned* sW2 = smu + TE2 * SO2_STR;

    const int tid  = threadIdx.x;
    const int lane = tid & 31, warp = tid >> 5;
    const int lr = lane >> 2, lc = lane & 3;
    const int tile0 = blockIdx.x * TE2;

    if (tid < TE2) {
        int v = eli[tile0 + tid];
        sIdx[tid] = ((unsigned)v < N_NODES) ? v : 0;
    } else {
        int v = eli[N_LABEL + tile0 + tid - TE2];
        sIdx[tid] = ((unsigned)v < N_NODES) ? v : 0;
    }
    __syncthreads();

    const float4* z4  = (const float4*)g_z;
    const float4* b14 = (const float4*)b1;
    #pragma unroll
    for (int it = 0; it < 16; it++) {
        int idx = tid + 256 * it;
        int e = idx >> 5, c4 = idx & 31;
        int a = sIdx[e], b = sIdx[TE2 + e];
        float4 va = z4[(size_t)a * 32 + c4];
        float4 vb = z4[(size_t)b * 32 + c4];
        float4 bi = b14[c4];
        ((uint4*)sO)[e * 33 + c4] = make_uint4(
            f2tf(fmaxf(vb.x - va.x + bi.x, 0.f)),
            f2tf(fmaxf(vb.y - va.y + bi.y, 0.f)),
            f2tf(fmaxf(vb.z - va.z + bi.z, 0.f)),
            f2tf(fmaxf(vb.w - va.w + bi.w, 0.f)));
    }
    #pragma unroll
    for (int it = 0; it < 16; it++) {
        int idx = tid + 256 * it;
        int k = idx >> 5, n = idx & 31;
        sW2[k * SW2_STR + n] = f2tf(W2[idx]);
    }
    __syncthreads();

    float c[4][4];
    #pragma unroll
    for (int nt = 0; nt < 4; nt++)
        #pragma unroll
        for (int i = 0; i < 4; i++) c[nt][i] = 0.f;

    #pragma unroll
    for (int k8 = 0; k8 < 16; k8++) {
        int kc = k8 * 8 + lc;
        int r = warp * 16 + lr;
        unsigned a[4];
        a[0] = sO[r * SO2_STR + kc];
        a[1] = sO[(r + 8) * SO2_STR + kc];
        a[2] = sO[r * SO2_STR + kc + 4];
        a[3] = sO[(r + 8) * SO2_STR + kc + 4];
        #pragma unroll
        for (int nt = 0; nt < 4; nt++) {
            int cb = nt * 8 + lr;
            unsigned b0 = sW2[kc * SW2_STR + cb];
            unsigned b1v = sW2[(kc + 4) * SW2_STR + cb];
            mma_tf32(c[nt], a, b0, b1v);
        }
    }

    const float b3r = b3[0];
    float p0 = 0.f, p1 = 0.f;
    #pragma unroll
    for (int nt = 0; nt < 4; nt++) {
        int n0 = nt * 8 + 2 * lc;
        float b20 = b2[n0], b21 = b2[n0 + 1];
        float w30 = W3[n0], w31 = W3[n0 + 1];
        p0 += fmaxf(c[nt][0] + b20, 0.f) * w30 + fmaxf(c[nt][1] + b21, 0.f) * w31;
        p1 += fmaxf(c[nt][2] + b20, 0.f) * w30 + fmaxf(c[nt][3] + b21, 0.f) * w31;
    }
    p0 += __shfl_xor_sync(0xffffffffu, p0, 1);
    p0 += __shfl_xor_sync(0xffffffffu, p0, 2);
    p1 += __shfl_xor_sync(0xffffffffu, p1, 1);
    p1 += __shfl_xor_sync(0xffffffffu, p1, 2);
    if (lc == 0) {
        int r = tile0 + warp * 16 + lr;
        out[r] = p0 + b3r;
        out[r + 8] = p1 + b3r;
    }
}

// ---------------------------------------------------------------------------
// Host: resolve inputs BY ELEMENT COUNT; y-gemm is launch #4 (ncu window).
// ---------------------------------------------------------------------------
extern "C" void kernel_launch(void* const* d_in, const int* in_sizes, int n_in,
                              void* d_out, int out_size) {
    const float *x = 0, *W_gcn = 0, *b_gcn = 0, *W1 = 0, *b1 = 0, *W2 = 0,
                *b2 = 0, *W3 = 0, *b3 = 0;
    const int *ei = 0, *eli = 0;
    int idx32[2] = {-1, -1};
    int n32 = 0, i128 = -1;

    for (int i = 0; i < n_in; i++) {
        switch (in_sizes[i]) {
            case 25600000: x     = (const float*)d_in[i]; break;
            case 1600000:  ei    = (const int*)d_in[i];   break;
            case 800000:   eli   = (const int*)d_in[i];   break;
            case 65536:    W_gcn = (const float*)d_in[i]; break;
            case 32768:    W1    = (const float*)d_in[i]; break;
            case 4096:     W2    = (const float*)d_in[i]; break;
            case 256:      b_gcn = (const float*)d_in[i]; break;
            case 128:      b1    = (const float*)d_in[i]; i128 = i; break;
            case 32:       if (n32 < 2) idx32[n32] = i; n32++; break;
            case 1:        b3    = (const float*)d_in[i]; break;
            default: break;
        }
    }
    if (n32 >= 2) {
        if (idx32[0] < i128) {
            W3 = (const float*)d_in[idx32[0]];
            b2 = (const float*)d_in[idx32[1]];
        } else {
            b2 = (const float*)d_in[idx32[0]];
            W3 = (const float*)d_in[idx32[1]];
        }
    }
    if (!x)     x     = (const float*)d_in[0];
    if (!ei)    ei    = (const int*)d_in[1];
    if (!eli)   eli   = (const int*)d_in[2];
    if (!W_gcn) W_gcn = (const float*)d_in[3];
    if (!b_gcn) b_gcn = (const float*)d_in[4];
    if (!W1)    W1    = (const float*)d_in[5];
    if (!b1)    b1    = (const float*)d_in[6];
    if (!W2)    W2    = (const float*)d_in[7];
    if (!b2)    b2    = (const float*)d_in[8];
    if (!W3)    W3    = (const float*)d_in[9];
    if (!b3)    b3    = (const float*)d_in[10];
    float* out = (float*)d_out;

    cudaFuncSetAttribute(gemm_tf32<H1>, cudaFuncAttributeMaxDynamicSharedMemorySize,
                         GSMEM2_B);
    cudaFuncSetAttribute(mlp2_kernel, cudaFuncAttributeMaxDynamicSharedMemorySize,
                         MLP2_SMEM_B);

    float* y = 0;
    cudaGetSymbolAddress((void**)&y, g_y);
    float* wc = 0;
    cudaGetSymbolAddress((void**)&wc, g_wc);

    zero_cnt<<<(N_NODES + 255) / 256, 256>>>();
    hist<<<(N_EDGES + 255) / 256, 256>>>(ei);

    // Wc = W_gcn @ W1 (fp32, tiny)
    wc_kernel<<<CH, 128>>>(W_gcn, W1);

    // launch #4 (ncu window): y = x @ Wc   — THE GEMM (x streamed once)
    dim3 g1(1, (N_NODES + 127) / 128);
    gemm_tf32<H1><<<g1, 256, GSMEM2_B>>>(x, wc, y);

    scan1<<<NBLK_SCAN, SCAN_CHUNK>>>();
    scan2<<<1, 256>>>();
    scan3<<<NBLK_SCAN, SCAN_CHUNK>>>();
    fill<<<(N_EDGES + 255) / 256, 256>>>(ei);
    gather128<<<(N_NODES + 7) / 8, 256>>>();

    mlp2_kernel<<<N_LABEL / TE2, 256, MLP2_SMEM_B>>>(eli, b1, W2, b2, W3, b3, out);
}

// round 15
// speedup vs baseline: 1.3892x; 1.0083x over previous
#include <cuda_runtime.h>

#define N_NODES 100000
#define N_EDGES 800000
#define N_LABEL 400000
#define CH      256
#define H1      128
#define H2      32

#define SCAN_CHUNK 512
#define NBLK_SCAN  ((N_NODES + SCAN_CHUNK - 1) / SCAN_CHUNK)   // 196

// Scratch (module-load allocated; allowed per harness rules)
__device__ __align__(16) float g_wc[CH * H1];
__device__ __align__(16) float g_y[(size_t)N_NODES * H1];
__device__ __align__(16) float g_z[(size_t)N_NODES * H1];
__device__ float g_dis[N_NODES];
__device__ int   g_cnt[N_NODES];
__device__ int   g_rowptr[N_NODES + 1];
__device__ int   g_cursor[N_NODES];
__device__ int   g_csrc[N_EDGES];
__device__ int   g_partial[NBLK_SCAN];
__device__ int   g_poff[NBLK_SCAN];

// ---------------------------------------------------------------------------
// tf32 mma helpers (m16n8k8, row.col, fp32 accumulate)
// ---------------------------------------------------------------------------
__device__ __forceinline__ unsigned f2tf(float f) {
    unsigned r;
    asm("cvt.rna.tf32.f32 %0, %1;" : "=r"(r) : "f"(f));
    return r;
}

__device__ __forceinline__ uint4 f2tf4(float4 v) {
    return make_uint4(f2tf(v.x), f2tf(v.y), f2tf(v.z), f2tf(v.w));
}

__device__ __forceinline__ void mma_tf32(float* c, const unsigned* a,
                                         unsigned b0, unsigned b1) {
    asm("mma.sync.aligned.m16n8k8.row.col.f32.tf32.tf32.f32 "
        "{%0,%1,%2,%3},{%4,%5,%6,%7},{%8,%9},{%0,%1,%2,%3};"
        : "+f"(c[0]), "+f"(c[1]), "+f"(c[2]), "+f"(c[3])
        : "r"(a[0]), "r"(a[1]), "r"(a[2]), "r"(a[3]), "r"(b0), "r"(b1));
}

// ---------------------------------------------------------------------------
// Wc = W_gcn @ W1 (256x256 @ 256x128, fp32, exact). 4 independent acc chains
// (the single-chain version serialized 256 x 4-cyc FADDs -> ~22 us).
// ---------------------------------------------------------------------------
__global__ void __launch_bounds__(128)
wc_kernel(const float* __restrict__ Wg, const float* __restrict__ W1) {
    __shared__ float srow[CH];
    int i = blockIdx.x;
    int j = threadIdx.x;
    for (int k = j; k < CH; k += 128) srow[k] = Wg[i * CH + k];
    __syncthreads();
    float a0 = 0.f, a1 = 0.f, a2 = 0.f, a3 = 0.f;
    #pragma unroll 8
    for (int k = 0; k < CH; k += 4) {
        a0 += srow[k]     * W1[(k)     * H1 + j];
        a1 += srow[k + 1] * W1[(k + 1) * H1 + j];
        a2 += srow[k + 2] * W1[(k + 2) * H1 + j];
        a3 += srow[k + 3] * W1[(k + 3) * H1 + j];
    }
    g_wc[i * H1 + j] = (a0 + a1) + (a2 + a3);
}

// ---------------------------------------------------------------------------
// Pipelined tf32 GEMM: OUT = X[Nx256] @ W[256xND]. Block tile 128x128,
// 8 warps (4m x 2n), warp tile 32x64, k-chunks of 32, double-buffered smem,
// reg prefetch, 1 sync/chunk. __launch_bounds__(256,2): cap regs so TWO CTAs
// fit the 64K regfile (round-14 profile: regs=128 -> 1 CTA, issue 32%).
// ---------------------------------------------------------------------------
#define GA_F     (128 * 36)
#define GB_F     (32 * 136)
#define GBUF2_F  (GA_F + GB_F)                 // 8960 words per buffer
#define GSMEM2_B (2 * GBUF2_F * 4)             // 71680 bytes

template<int ND>
__global__ void __launch_bounds__(256, 2)
gemm_tf32(const float* __restrict__ X, const float* __restrict__ W,
          float* __restrict__ OUT) {
    extern __shared__ __align__(16) unsigned smu[];
    const int tid = threadIdx.x;
    const int lane = tid & 31, warp = tid >> 5;
    const int warp_m = warp >> 1, warp_n = warp & 1;
    const int row0 = blockIdx.y * 128, col0 = blockIdx.x * 128;
    const int lr = lane >> 2, lc = lane & 3;

    const int ar = tid >> 3, ac4 = tid & 7;
    const int bk = tid >> 5, bc4 = tid & 31;

    float c[2][8][4];
    #pragma unroll
    for (int mt = 0; mt < 2; mt++)
        #pragma unroll
        for (int nt = 0; nt < 8; nt++)
            #pragma unroll
            for (int i = 0; i < 4; i++) c[mt][nt][i] = 0.f;

    float4 ra[4], rb[4];

    #pragma unroll
    for (int it = 0; it < 4; it++) {
        int grow = row0 + ar + 32 * it;
        ra[it] = make_float4(0.f, 0.f, 0.f, 0.f);
        if (grow < N_NODES)
            ra[it] = *(const float4*)&X[(size_t)grow * CH + ac4 * 4];
    }
    #pragma unroll
    for (int it = 0; it < 4; it++)
        rb[it] = *(const float4*)&W[(size_t)(bk + 8 * it) * ND + col0 + bc4 * 4];

    int buf = 0;
    for (int cch = 0; cch < 8; cch++) {
        unsigned* sA = smu + buf * GBUF2_F;
        unsigned* sB = sA + GA_F;
        #pragma unroll
        for (int it = 0; it < 4; it++)
            ((uint4*)sA)[(ar + 32 * it) * 9 + ac4] = f2tf4(ra[it]);
        #pragma unroll
        for (int it = 0; it < 4; it++)
            ((uint4*)sB)[(bk + 8 * it) * 34 + bc4] = f2tf4(rb[it]);
        __syncthreads();

        if (cch < 7) {
            int k0 = (cch + 1) * 32;
            #pragma unroll
            for (int it = 0; it < 4; it++) {
                int grow = row0 + ar + 32 * it;
                ra[it] = make_float4(0.f, 0.f, 0.f, 0.f);
                if (grow < N_NODES)
                    ra[it] = *(const float4*)&X[(size_t)grow * CH + k0 + ac4 * 4];
            }
            #pragma unroll
            for (int it = 0; it < 4; it++)
                rb[it] = *(const float4*)&W[(size_t)(k0 + bk + 8 * it) * ND + col0 + bc4 * 4];
        }

        #pragma unroll
        for (int k8 = 0; k8 < 4; k8++) {
            int kc = k8 * 8 + lc;
            unsigned a[2][4];
            #pragma unroll
            for (int mt = 0; mt < 2; mt++) {
                int r = warp_m * 32 + mt * 16 + lr;
                a[mt][0] = sA[r * 36 + kc];
                a[mt][1] = sA[(r + 8) * 36 + kc];
                a[mt][2] = sA[r * 36 + kc + 4];
                a[mt][3] = sA[(r + 8) * 36 + kc + 4];
            }
            #pragma unroll
            for (int nt = 0; nt < 8; nt++) {
                int cb = warp_n * 64 + nt * 8 + lr;
                unsigned b0 = sB[kc * 136 + cb];
                unsigned b1 = sB[(kc + 4) * 136 + cb];
                mma_tf32(c[0][nt], a[0], b0, b1);
                mma_tf32(c[1][nt], a[1], b0, b1);
            }
        }
        buf ^= 1;
    }

    #pragma unroll
    for (int mt = 0; mt < 2; mt++) {
        int r0 = row0 + warp_m * 32 + mt * 16 + lr;
        #pragma unroll
        for (int nt = 0; nt < 8; nt++) {
            int cc = col0 + warp_n * 64 + nt * 8 + 2 * lc;
            if (r0 < N_NODES)
                *(float2*)&OUT[(size_t)r0 * ND + cc] = make_float2(c[mt][nt][0], c[mt][nt][1]);
            if (r0 + 8 < N_NODES)
                *(float2*)&OUT[(size_t)(r0 + 8) * ND + cc] = make_float2(c[mt][nt][2], c[mt][nt][3]);
        }
    }
}

// ---------------------------------------------------------------------------
// CSR build: histogram -> 3-pass exclusive scan -> bucket fill
// ---------------------------------------------------------------------------
__global__ void zero_cnt() {
    int i = blockIdx.x * blockDim.x + threadIdx.x;
    if (i < N_NODES) g_cnt[i] = 0;
}

__global__ void hist(const int* __restrict__ ei) {
    int e = blockIdx.x * blockDim.x + threadIdx.x;
    if (e >= N_EDGES) return;
    int d = ei[N_EDGES + e];
    if ((unsigned)d < N_NODES) atomicAdd(&g_cnt[d], 1);
}

__global__ void __launch_bounds__(SCAN_CHUNK) scan1() {
    __shared__ int s[SCAN_CHUNK];
    int tid = threadIdx.x;
    int i = blockIdx.x * SCAN_CHUNK + tid;
    s[tid] = (i < N_NODES) ? g_cnt[i] : 0;
    __syncthreads();
    #pragma unroll
    for (int off = SCAN_CHUNK / 2; off > 0; off >>= 1) {
        if (tid < off) s[tid] += s[tid + off];
        __syncthreads();
    }
    if (tid == 0) g_partial[blockIdx.x] = s[0];
}

__global__ void __launch_bounds__(256) scan2() {
    __shared__ int s[256];
    int tid = threadIdx.x;
    int v = (tid < NBLK_SCAN) ? g_partial[tid] : 0;
    s[tid] = v;
    __syncthreads();
    #pragma unroll
    for (int off = 1; off < 256; off <<= 1) {
        int t = (tid >= off) ? s[tid - off] : 0;
        __syncthreads();
        s[tid] += t;
        __syncthreads();
    }
    if (tid < NBLK_SCAN) g_poff[tid] = s[tid] - v;
    if (tid == NBLK_SCAN - 1) g_rowptr[N_NODES] = s[tid];
}

__global__ void __launch_bounds__(SCAN_CHUNK) scan3() {
    __shared__ int s[SCAN_CHUNK];
    int tid = threadIdx.x;
    int i = blockIdx.x * SCAN_CHUNK + tid;
    int c = (i < N_NODES) ? g_cnt[i] : 0;
    s[tid] = c;
    __syncthreads();
    #pragma unroll
    for (int off = 1; off < SCAN_CHUNK; off <<= 1) {
        int t = (tid >= off) ? s[tid - off] : 0;
        __syncthreads();
        s[tid] += t;
        __syncthreads();
    }
    if (i < N_NODES) {
        int excl = g_poff[blockIdx.x] + s[tid] - c;
        g_rowptr[i] = excl;
        g_cursor[i] = excl;
        g_dis[i] = rsqrtf((float)(c + 1));
    }
}

__global__ void fill(const int* __restrict__ ei) {
    int e = blockIdx.x * blockDim.x + threadIdx.x;
    if (e >= N_EDGES) return;
    int src = ei[e];
    int dst = ei[N_EDGES + e];
    if ((unsigned)src >= N_NODES || (unsigned)dst >= N_NODES) return;
    int p = atomicAdd(&g_cursor[dst], 1);
    g_csrc[p] = src;
}

// ---------------------------------------------------------------------------
// Gather on y (128-wide), unroll x2: two independent edge-row loads in flight.
// z[i] = dis_i*(dis_i*y[i] + sum_{s in in(i)} dis_s*y[s])
// ---------------------------------------------------------------------------
__global__ void __launch_bounds__(256) gather128() {
    int node = blockIdx.x * 8 + (threadIdx.x >> 5);
    if (node >= N_NODES) return;
    int lane = threadIdx.x & 31;
    const float4* y4 = (const float4*)g_y;

    float di = g_dis[node];
    float4 v = y4[(size_t)node * 32 + lane];
    float4 acc = make_float4(di * v.x, di * v.y, di * v.z, di * v.w);
    float4 acc2 = make_float4(0.f, 0.f, 0.f, 0.f);

    int beg = g_rowptr[node], end = g_rowptr[node + 1];
    int j = beg;
    for (; j + 1 < end; j += 2) {
        int s0 = g_csrc[j];
        int s1 = g_csrc[j + 1];
        float c0 = g_dis[s0];
        float c1 = g_dis[s1];
        float4 w0 = y4[(size_t)s0 * 32 + lane];
        float4 w1 = y4[(size_t)s1 * 32 + lane];
        acc.x  += c0 * w0.x; acc.y  += c0 * w0.y;
        acc.z  += c0 * w0.z; acc.w  += c0 * w0.w;
        acc2.x += c1 * w1.x; acc2.y += c1 * w1.y;
        acc2.z += c1 * w1.z; acc2.w += c1 * w1.w;
    }
    if (j < end) {
        int s0 = g_csrc[j];
        float c0 = g_dis[s0];
        float4 w0 = y4[(size_t)s0 * 32 + lane];
        acc.x += c0 * w0.x; acc.y += c0 * w0.y;
        acc.z += c0 * w0.z; acc.w += c0 * w0.w;
    }
    acc.x += acc2.x; acc.y += acc2.y; acc.z += acc2.z; acc.w += acc2.w;

    ((float4*)g_z)[(size_t)node * 32 + lane] =
        make_float4(di * acc.x, di * acc.y, di * acc.z, di * acc.w);
}

// ---------------------------------------------------------------------------
// Edge MLP (round-14 PASS, unchanged): 128 edges/block, layer-2 on mma.
// ---------------------------------------------------------------------------
#define TE2       128
#define SO2_STR   132
#define SW2_STR   40
#define MLP2_SMEM_W (TE2 * SO2_STR + H1 * SW2_STR)
#define MLP2_SMEM_B (MLP2_SMEM_W * 4)

__global__ void __launch_bounds__(256)
mlp2_kernel(const int* __restrict__ eli,
            const float* __restrict__ b1, const float* __restrict__ W2,
            const float* __restrict__ b2, const float* __restrict__ W3,
            const float* __restrict__ b3, float* __restrict__ out) {
    extern __shared__ __align__(16) unsigned smu[];
    __shared__ int sIdx[2 * TE2];

    unsigned* sO  = smu;
    unsigned* sW2 = smu + TE2 * SO2_STR;

    const int tid  = threadIdx.x;
    const int lane = tid & 31, warp = tid >> 5;
    const int lr = lane >> 2, lc = lane & 3;
    const int tile0 = blockIdx.x * TE2;

    if (tid < TE2) {
        int v = eli[tile0 + tid];
        sIdx[tid] = ((unsigned)v < N_NODES) ? v : 0;
    } else {
        int v = eli[N_LABEL + tile0 + tid - TE2];
        sIdx[tid] = ((unsigned)v < N_NODES) ? v : 0;
    }
    __syncthreads();

    const float4* z4  = (const float4*)g_z;
    const float4* b14 = (const float4*)b1;
    #pragma unroll
    for (int it = 0; it < 16; it++) {
        int idx = tid + 256 * it;
        int e = idx >> 5, c4 = idx & 31;
        int a = sIdx[e], b = sIdx[TE2 + e];
        float4 va = z4[(size_t)a * 32 + c4];
        float4 vb = z4[(size_t)b * 32 + c4];
        float4 bi = b14[c4];
        ((uint4*)sO)[e * 33 + c4] = make_uint4(
            f2tf(fmaxf(vb.x - va.x + bi.x, 0.f)),
            f2tf(fmaxf(vb.y - va.y + bi.y, 0.f)),
            f2tf(fmaxf(vb.z - va.z + bi.z, 0.f)),
            f2tf(fmaxf(vb.w - va.w + bi.w, 0.f)));
    }
    #pragma unroll
    for (int it = 0; it < 16; it++) {
        int idx = tid + 256 * it;
        int k = idx >> 5, n = idx & 31;
        sW2[k * SW2_STR + n] = f2tf(W2[idx]);
    }
    __syncthreads();

    float c[4][4];
    #pragma unroll
    for (int nt = 0; nt < 4; nt++)
        #pragma unroll
        for (int i = 0; i < 4; i++) c[nt][i] = 0.f;

    #pragma unroll
    for (int k8 = 0; k8 < 16; k8++) {
        int kc = k8 * 8 + lc;
        int r = warp * 16 + lr;
        unsigned a[4];
        a[0] = sO[r * SO2_STR + kc];
        a[1] = sO[(r + 8) * SO2_STR + kc];
        a[2] = sO[r * SO2_STR + kc + 4];
        a[3] = sO[(r + 8) * SO2_STR + kc + 4];
        #pragma unroll
        for (int nt = 0; nt < 4; nt++) {
            int cb = nt * 8 + lr;
            unsigned b0 = sW2[kc * SW2_STR + cb];
            unsigned b1v = sW2[(kc + 4) * SW2_STR + cb];
            mma_tf32(c[nt], a, b0, b1v);
        }
    }

    const float b3r = b3[0];
    float p0 = 0.f, p1 = 0.f;
    #pragma unroll
    for (int nt = 0; nt < 4; nt++) {
        int n0 = nt * 8 + 2 * lc;
        float b20 = b2[n0], b21 = b2[n0 + 1];
        float w30 = W3[n0], w31 = W3[n0 + 1];
        p0 += fmaxf(c[nt][0] + b20, 0.f) * w30 + fmaxf(c[nt][1] + b21, 0.f) * w31;
        p1 += fmaxf(c[nt][2] + b20, 0.f) * w30 + fmaxf(c[nt][3] + b21, 0.f) * w31;
    }
    p0 += __shfl_xor_sync(0xffffffffu, p0, 1);
    p0 += __shfl_xor_sync(0xffffffffu, p0, 2);
    p1 += __shfl_xor_sync(0xffffffffu, p1, 1);
    p1 += __shfl_xor_sync(0xffffffffu, p1, 2);
    if (lc == 0) {
        int r = tile0 + warp * 16 + lr;
        out[r] = p0 + b3r;
        out[r + 8] = p1 + b3r;
    }
}

// ---------------------------------------------------------------------------
// Host: resolve inputs BY ELEMENT COUNT; y-gemm is launch #4 (ncu window).
// ---------------------------------------------------------------------------
extern "C" void kernel_launch(void* const* d_in, const int* in_sizes, int n_in,
                              void* d_out, int out_size) {
    const float *x = 0, *W_gcn = 0, *b_gcn = 0, *W1 = 0, *b1 = 0, *W2 = 0,
                *b2 = 0, *W3 = 0, *b3 = 0;
    const int *ei = 0, *eli = 0;
    int idx32[2] = {-1, -1};
    int n32 = 0, i128 = -1;

    for (int i = 0; i < n_in; i++) {
        switch (in_sizes[i]) {
            case 25600000: x     = (const float*)d_in[i]; break;
            case 1600000:  ei    = (const int*)d_in[i];   break;
            case 800000:   eli   = (const int*)d_in[i];   break;
            case 65536:    W_gcn = (const float*)d_in[i]; break;
            case 32768:    W1    = (const float*)d_in[i]; break;
            case 4096:     W2    = (const float*)d_in[i]; break;
            case 256:      b_gcn = (const float*)d_in[i]; break;
            case 128:      b1    = (const float*)d_in[i]; i128 = i; break;
            case 32:       if (n32 < 2) idx32[n32] = i; n32++; break;
            case 1:        b3    = (const float*)d_in[i]; break;
            default: break;
        }
    }
    if (n32 >= 2) {
        if (idx32[0] < i128) {
            W3 = (const float*)d_in[idx32[0]];
            b2 = (const float*)d_in[idx32[1]];
        } else {
            b2 = (const float*)d_in[idx32[0]];
            W3 = (const float*)d_in[idx32[1]];
        }
    }
    if (!x)     x     = (const float*)d_in[0];
    if (!ei)    ei    = (const int*)d_in[1];
    if (!eli)   eli   = (const int*)d_in[2];
    if (!W_gcn) W_gcn = (const float*)d_in[3];
    if (!b_gcn) b_gcn = (const float*)d_in[4];
    if (!W1)    W1    = (const float*)d_in[5];
    if (!b1)    b1    = (const float*)d_in[6];
    if (!W2)    W2    = (const float*)d_in[7];
    if (!b2)    b2    = (const float*)d_in[8];
    if (!W3)    W3    = (const float*)d_in[9];
    if (!b3)    b3    = (const float*)d_in[10];
    float* out = (float*)d_out;

    cudaFuncSetAttribute(gemm_tf32<H1>, cudaFuncAttributeMaxDynamicSharedMemorySize,
                         GSMEM2_B);
    cudaFuncSetAttribute(mlp2_kernel, cudaFuncAttributeMaxDynamicSharedMemorySize,
                         MLP2_SMEM_B);

    float* y = 0;
    cudaGetSymbolAddress((void**)&y, g_y);
    float* wc = 0;
    cudaGetSymbolAddress((void**)&wc, g_wc);

    zero_cnt<<<(N_NODES + 255) / 256, 256>>>();
    hist<<<(N_EDGES + 255) / 256, 256>>>(ei);

    // Wc = W_gcn @ W1 (fp32, tiny)
    wc_kernel<<<CH, 128>>>(W_gcn, W1);

    // launch #4 (ncu window): y = x @ Wc
    dim3 g1(1, (N_NODES + 127) / 128);
    gemm_tf32<H1><<<g1, 256, GSMEM2_B>>>(x, wc, y);

    scan1<<<NBLK_SCAN, SCAN_CHUNK>>>();
    scan2<<<1, 256>>>();
    scan3<<<NBLK_SCAN, SCAN_CHUNK>>>();
    fill<<<(N_EDGES + 255) / 256, 256>>>(ei);
    gather128<<<(N_NODES + 7) / 8, 256>>>();

    mlp2_kernel<<<N_LABEL / TE2, 256, MLP2_SMEM_B>>>(eli, b1, W2, b2, W3, b3, out);
}